// round 11
// baseline (speedup 1.0000x reference)
#include <cuda_runtime.h>
#include <cuda_fp16.h>
#include <mma.h>
using namespace nvcuda;

#define N_NODES 100000
#define D 128
#define N_EDGES 3200000
#define CAP 160          // per-node adjacency capacity; Poisson(64) => P(deg>=160) ~ e^-50

// ---- scratch (__device__ globals: allocation-free rule; zero at module load) ----
__device__ __half g_feath[(size_t)N_NODES * D];     // fp16 features
__device__ __half g_meanh[(size_t)N_NODES * D];     // fp16 neighbor means
__device__ __half g_Wh[2 * D * D];                  // fp16 weights
__device__ int    g_cur[N_NODES];                   // fill cursors (re-zeroed by aggregate)
__device__ int    g_adj[(size_t)N_NODES * CAP];     // bucketed adjacency (64MB)

// ---------------------------------------------------------------------------
// 1) fused prep: convert features+W to fp16 AND fill adjacency buckets.
//    The two jobs are independent; DRAM-bound convert hides under the
//    atomic-bound fill. g_cur is guaranteed zero on entry (module-load zero
//    on the first call, re-zeroed by aggregate_kernel on every later call).
// ---------------------------------------------------------------------------
__global__ void __launch_bounds__(256) prep_kernel(const float* __restrict__ feat,
                                                   const float* __restrict__ W,
                                                   const int*   __restrict__ src,
                                                   const int*   __restrict__ dst) {
    int i = blockIdx.x * blockDim.x + threadIdx.x;
    int stride = gridDim.x * blockDim.x;

    // -- convert features
    const int totalF = N_NODES * D / 4;
    const float4* f4 = reinterpret_cast<const float4*>(feat);
    for (int k = i; k < totalF; k += stride) {
        float4 v = f4[k];
        __half2 h0 = __floats2half2_rn(v.x, v.y);
        __half2 h1 = __floats2half2_rn(v.z, v.w);
        uint2 u;
        u.x = *reinterpret_cast<unsigned int*>(&h0);
        u.y = *reinterpret_cast<unsigned int*>(&h1);
        *reinterpret_cast<uint2*>(g_feath + (size_t)k * 4) = u;
    }
    // -- convert W
    const int totalW = 2 * D * D / 4;
    const float4* w4 = reinterpret_cast<const float4*>(W);
    for (int k = i; k < totalW; k += stride) {
        float4 v = w4[k];
        __half2 h0 = __floats2half2_rn(v.x, v.y);
        __half2 h1 = __floats2half2_rn(v.z, v.w);
        uint2 u;
        u.x = *reinterpret_cast<unsigned int*>(&h0);
        u.y = *reinterpret_cast<unsigned int*>(&h1);
        *reinterpret_cast<uint2*>(g_Wh + (size_t)k * 4) = u;
    }
    // -- fill adjacency
    const int4* s4 = reinterpret_cast<const int4*>(src);
    const int4* d4 = reinterpret_cast<const int4*>(dst);
    for (int e = i; e < N_EDGES / 4; e += stride) {
        int4 s = s4[e], d = d4[e];
        int sl;
        sl = atomicAdd(&g_cur[s.x], 1); if (sl < CAP) g_adj[(size_t)s.x * CAP + sl] = d.x;
        sl = atomicAdd(&g_cur[d.x], 1); if (sl < CAP) g_adj[(size_t)d.x * CAP + sl] = s.x;
        sl = atomicAdd(&g_cur[s.y], 1); if (sl < CAP) g_adj[(size_t)s.y * CAP + sl] = d.y;
        sl = atomicAdd(&g_cur[d.y], 1); if (sl < CAP) g_adj[(size_t)d.y * CAP + sl] = s.y;
        sl = atomicAdd(&g_cur[s.z], 1); if (sl < CAP) g_adj[(size_t)s.z * CAP + sl] = d.z;
        sl = atomicAdd(&g_cur[d.z], 1); if (sl < CAP) g_adj[(size_t)d.z * CAP + sl] = s.z;
        sl = atomicAdd(&g_cur[s.w], 1); if (sl < CAP) g_adj[(size_t)s.w * CAP + sl] = d.w;
        sl = atomicAdd(&g_cur[d.w], 1); if (sl < CAP) g_adj[(size_t)d.w * CAP + sl] = s.w;
    }
}

// ---------------------------------------------------------------------------
// 2) gather aggregation: warp per node, lane owns 4 fp16 cols, fp32 accum.
//    Re-zeroes g_cur[node] after reading (restores invariant for next replay).
// ---------------------------------------------------------------------------
__global__ void __launch_bounds__(256) aggregate_kernel() {
    int node = (blockIdx.x * blockDim.x + threadIdx.x) >> 5;
    int lane = threadIdx.x & 31;
    if (node >= N_NODES) return;

    const int cnt = g_cur[node];                 // true degree
    if (lane == 0) g_cur[node] = 0;              // reset for next replay
    const int c   = min(cnt, CAP);               // stored entries
    const int* adj = g_adj + (size_t)node * CAP;
    const int col = lane * 4;

    float4 acc = make_float4(0.f, 0.f, 0.f, 0.f);

    int j = 0;
    for (; j + 3 < c; j += 4) {
        int nb0 = __ldg(&adj[j]);
        int nb1 = __ldg(&adj[j + 1]);
        int nb2 = __ldg(&adj[j + 2]);
        int nb3 = __ldg(&adj[j + 3]);
        uint2 u0 = *reinterpret_cast<const uint2*>(g_feath + (size_t)nb0 * D + col);
        uint2 u1 = *reinterpret_cast<const uint2*>(g_feath + (size_t)nb1 * D + col);
        uint2 u2 = *reinterpret_cast<const uint2*>(g_feath + (size_t)nb2 * D + col);
        uint2 u3 = *reinterpret_cast<const uint2*>(g_feath + (size_t)nb3 * D + col);
        float2 a0 = __half22float2(*reinterpret_cast<__half2*>(&u0.x));
        float2 a1 = __half22float2(*reinterpret_cast<__half2*>(&u0.y));
        float2 b0 = __half22float2(*reinterpret_cast<__half2*>(&u1.x));
        float2 b1 = __half22float2(*reinterpret_cast<__half2*>(&u1.y));
        float2 c0 = __half22float2(*reinterpret_cast<__half2*>(&u2.x));
        float2 c1 = __half22float2(*reinterpret_cast<__half2*>(&u2.y));
        float2 d0 = __half22float2(*reinterpret_cast<__half2*>(&u3.x));
        float2 d1 = __half22float2(*reinterpret_cast<__half2*>(&u3.y));
        acc.x += (a0.x + b0.x) + (c0.x + d0.x);
        acc.y += (a0.y + b0.y) + (c0.y + d0.y);
        acc.z += (a1.x + b1.x) + (c1.x + d1.x);
        acc.w += (a1.y + b1.y) + (c1.y + d1.y);
    }
    for (; j < c; j++) {
        int nb = __ldg(&adj[j]);
        uint2 u = *reinterpret_cast<const uint2*>(g_feath + (size_t)nb * D + col);
        float2 f0 = __half22float2(*reinterpret_cast<__half2*>(&u.x));
        float2 f1 = __half22float2(*reinterpret_cast<__half2*>(&u.y));
        acc.x += f0.x; acc.y += f0.y; acc.z += f1.x; acc.w += f1.y;
    }

    float inv = 1.0f / (float)(cnt > 0 ? cnt : 1);
    __half2 o0 = __floats2half2_rn(acc.x * inv, acc.y * inv);
    __half2 o1 = __floats2half2_rn(acc.z * inv, acc.w * inv);
    uint2 u;
    u.x = *reinterpret_cast<unsigned int*>(&o0);
    u.y = *reinterpret_cast<unsigned int*>(&o1);
    *reinterpret_cast<uint2*>(g_meanh + (size_t)node * D + col) = u;
}

// ---------------------------------------------------------------------------
// 3) HMMA GEMM: out = relu([feat | mean] @ W + b).
//    256 threads, BM=64, BN=128, BK=32 double-buffered cp.async.
//    Warp tile 32x32, 8 warps -> ~90 regs -> 2 CTAs/SM (independent barriers).
// ---------------------------------------------------------------------------
#define GBM 64
#define GBK2 32
#define A_LD2 40           // 32 + 8 pad halfs (80B stride)
#define W_LD2 136          // 128 + 8 pad halfs (272B stride)
#define AS_BYTES (2 * GBM * A_LD2 * 2)      // 10240
#define WS_BYTES (2 * GBK2 * W_LD2 * 2)     // 17408

__device__ __forceinline__ void cp16(void* smem_dst, const void* gsrc) {
    unsigned s = (unsigned)__cvta_generic_to_shared(smem_dst);
    asm volatile("cp.async.cg.shared.global [%0], [%1], 16;" :: "r"(s), "l"(gsrc) : "memory");
}
__device__ __forceinline__ void cp_commit() {
    asm volatile("cp.async.commit_group;" ::: "memory");
}
__device__ __forceinline__ void cp_wait0() {
    asm volatile("cp.async.wait_group 0;" ::: "memory");
}

__global__ void __launch_bounds__(256) gemm_kernel(const int*   __restrict__ nodes,
                                                   const float* __restrict__ bias,
                                                   float*       __restrict__ out) {
    __shared__ __align__(16) unsigned char smem_raw[AS_BYTES + WS_BYTES];  // 27648B
    __half* Asb = reinterpret_cast<__half*>(smem_raw);                 // [2][64*40]
    __half* Wsb = reinterpret_cast<__half*>(smem_raw + AS_BYTES);      // [2][32*136]

    const int tid = threadIdx.x;
    const int m0  = blockIdx.x * GBM;

    // A staging: 64 rows x 32 halfs (64B) = 256 x 16B -> 1 cp16/thread
    const int arow  = tid >> 2;
    const int acol8 = (tid & 3) * 8;
    const int anode = nodes[min(m0 + arow, N_NODES - 1)];
    // W staging: 32 rows x 128 halfs = 512 x 16B -> 2 cp16/thread

    const int wid = tid >> 5;
    const int wm  = wid >> 2;        // 0..1 : rows [wm*32, +32)
    const int wn  = wid & 3;         // 0..3 : cols [wn*32, +32)

    wmma::fragment<wmma::accumulator, 16, 16, 16, float> c[2][2];
    #pragma unroll
    for (int i = 0; i < 2; i++)
        #pragma unroll
        for (int j = 0; j < 2; j++) wmma::fill_fragment(c[i][j], 0.0f);

    // prefetch chunk 0
    {
        cp16(Asb + arow * A_LD2 + acol8, g_feath + (size_t)anode * D + acol8);
        #pragma unroll
        for (int j = 0; j < 2; j++) {
            int g    = tid * 2 + j;
            int wrow = g >> 4;
            int wc8  = (g & 15) * 8;
            cp16(Wsb + wrow * W_LD2 + wc8, g_Wh + (size_t)wrow * 128 + wc8);
        }
        cp_commit();
    }
    cp_wait0();
    __syncthreads();

    #pragma unroll
    for (int kc = 0; kc < 8; kc++) {
        const int buf = kc & 1;
        if (kc < 7) {
            const int kn = kc + 1;
            const __half* basep = (kn < 4)
                ? (g_feath + (size_t)anode * D + kn * 32)
                : (g_meanh + (size_t)anode * D + (kn - 4) * 32);
            cp16(Asb + (buf ^ 1) * GBM * A_LD2 + arow * A_LD2 + acol8, basep + acol8);
            #pragma unroll
            for (int j = 0; j < 2; j++) {
                int g    = tid * 2 + j;
                int wrow = g >> 4;
                int wc8  = (g & 15) * 8;
                cp16(Wsb + (buf ^ 1) * GBK2 * W_LD2 + wrow * W_LD2 + wc8,
                     g_Wh + (size_t)(kn * GBK2 + wrow) * 128 + wc8);
            }
            cp_commit();
        }

        const __half* Ab = Asb + buf * GBM * A_LD2;
        const __half* Wb = Wsb + buf * GBK2 * W_LD2;
        #pragma unroll
        for (int kkk = 0; kkk < 2; kkk++) {
            wmma::fragment<wmma::matrix_a, 16, 16, 16, __half, wmma::row_major> a[2];
            wmma::load_matrix_sync(a[0], Ab + (wm * 32 + 0)  * A_LD2 + kkk * 16, A_LD2);
            wmma::load_matrix_sync(a[1], Ab + (wm * 32 + 16) * A_LD2 + kkk * 16, A_LD2);
            wmma::fragment<wmma::matrix_b, 16, 16, 16, __half, wmma::row_major> b[2];
            wmma::load_matrix_sync(b[0], Wb + (kkk * 16) * W_LD2 + wn * 32,      W_LD2);
            wmma::load_matrix_sync(b[1], Wb + (kkk * 16) * W_LD2 + wn * 32 + 16, W_LD2);
            #pragma unroll
            for (int i = 0; i < 2; i++)
                #pragma unroll
                for (int j = 0; j < 2; j++)
                    wmma::mma_sync(c[i][j], a[i], b[j], c[i][j]);
        }

        if (kc < 7) {
            cp_wait0();
            __syncthreads();
        }
    }
    __syncthreads();

    // ---- epilogue: two 32-row passes through reused smem (16KB f32 staging)
    float* Cs = reinterpret_cast<float*>(smem_raw);    // 32*128*4 = 16384B
    const int erow = tid >> 3;                         // 0..31
    const int eseg = (tid & 7) * 16;                   // 16 cols per thread
    #pragma unroll
    for (int half = 0; half < 2; half++) {
        if (wm == half) {
            #pragma unroll
            for (int i = 0; i < 2; i++)
                #pragma unroll
                for (int j = 0; j < 2; j++)
                    wmma::store_matrix_sync(Cs + (i * 16) * 128 + wn * 32 + j * 16,
                                            c[i][j], 128, wmma::mem_row_major);
        }
        __syncthreads();
        int m = m0 + half * 32 + erow;
        if (m < N_NODES) {
            #pragma unroll
            for (int q = 0; q < 4; q++) {
                int col = eseg + q * 4;
                float4 v  = *reinterpret_cast<float4*>(Cs + erow * 128 + col);
                float4 bv = *reinterpret_cast<const float4*>(bias + col);
                v.x = fmaxf(v.x + bv.x, 0.f);
                v.y = fmaxf(v.y + bv.y, 0.f);
                v.z = fmaxf(v.z + bv.z, 0.f);
                v.w = fmaxf(v.w + bv.w, 0.f);
                *reinterpret_cast<float4*>(out + (size_t)m * 128 + col) = v;
            }
        }
        __syncthreads();
    }
}

// ---------------------------------------------------------------------------
// kernel_launch
// Inputs: nodes[i32 100000], features[f32 100000*128], edge_index[i32 2*3.2M],
//         W[f32 256*128], b[f32 128]. Output f32 [100000*128].
// ---------------------------------------------------------------------------
extern "C" void kernel_launch(void* const* d_in, const int* in_sizes, int n_in,
                              void* d_out, int out_size) {
    const int*   nodes = (const int*)d_in[0];
    const float* feat  = (const float*)d_in[1];
    const int*   ei    = (const int*)d_in[2];
    const float* W     = (const float*)d_in[3];
    const float* bias  = (const float*)d_in[4];
    float*       out   = (float*)d_out;

    const int* src = ei;
    const int* dst = ei + N_EDGES;

    prep_kernel<<<3125, 256>>>(feat, W, src, dst);      // convert + fill fused
    aggregate_kernel<<<(N_NODES * 32 + 255) / 256, 256>>>();
    gemm_kernel<<<(N_NODES + GBM - 1) / GBM, 256>>>(nodes, bias, out);
}

// round 14
// speedup vs baseline: 2.0380x; 2.0380x over previous
#include <cuda_runtime.h>
#include <cuda_fp16.h>
#include <mma.h>
using namespace nvcuda;

#define N_NODES 100000
#define D 128
#define N_EDGES 3200000
#define CAP 160          // per-node adjacency capacity; Poisson(64) => P(deg>=160) ~ e^-50

// ---- scratch (__device__ globals: allocation-free rule) ----
__device__ __half g_feath[(size_t)N_NODES * D];     // fp16 features
__device__ __half g_meanh[(size_t)N_NODES * D];     // fp16 neighbor means
__device__ __half g_Wh[2 * D * D];                  // fp16 weights
__device__ int    g_cur[N_NODES];                   // degree counters / fill cursors
__device__ int    g_adj[(size_t)N_NODES * CAP];     // bucketed adjacency (64MB)

// ---------------------------------------------------------------------------
// 1) convert features + W to fp16, zero cursors (graph replays -> re-zero)
// ---------------------------------------------------------------------------
__global__ void __launch_bounds__(256) convert_kernel(const float* __restrict__ feat,
                                                      const float* __restrict__ W) {
    int i = blockIdx.x * blockDim.x + threadIdx.x;
    int stride = gridDim.x * blockDim.x;
    const int totalF = N_NODES * D / 4;
    const int totalW = 2 * D * D / 4;
    const float4* f4 = reinterpret_cast<const float4*>(feat);
    const float4* w4 = reinterpret_cast<const float4*>(W);
    for (int k = i; k < totalF; k += stride) {
        float4 v = f4[k];
        __half2 h0 = __floats2half2_rn(v.x, v.y);
        __half2 h1 = __floats2half2_rn(v.z, v.w);
        uint2 u;
        u.x = *reinterpret_cast<unsigned int*>(&h0);
        u.y = *reinterpret_cast<unsigned int*>(&h1);
        *reinterpret_cast<uint2*>(g_feath + (size_t)k * 4) = u;
    }
    for (int k = i; k < totalW; k += stride) {
        float4 v = w4[k];
        __half2 h0 = __floats2half2_rn(v.x, v.y);
        __half2 h1 = __floats2half2_rn(v.z, v.w);
        uint2 u;
        u.x = *reinterpret_cast<unsigned int*>(&h0);
        u.y = *reinterpret_cast<unsigned int*>(&h1);
        *reinterpret_cast<uint2*>(g_Wh + (size_t)k * 4) = u;
    }
    for (int k = i; k < N_NODES; k += stride) g_cur[k] = 0;
}

// ---------------------------------------------------------------------------
// 2) adjacency fill into fixed-stride buckets (no hist/scan needed)
// ---------------------------------------------------------------------------
__global__ void __launch_bounds__(256) fill_kernel(const int* __restrict__ src,
                                                   const int* __restrict__ dst) {
    int i = blockIdx.x * blockDim.x + threadIdx.x;
    int stride = gridDim.x * blockDim.x;
    const int4* s4 = reinterpret_cast<const int4*>(src);
    const int4* d4 = reinterpret_cast<const int4*>(dst);
    for (int e = i; e < N_EDGES / 4; e += stride) {
        int4 s = s4[e], d = d4[e];
        int sl;
        sl = atomicAdd(&g_cur[s.x], 1); if (sl < CAP) g_adj[(size_t)s.x * CAP + sl] = d.x;
        sl = atomicAdd(&g_cur[d.x], 1); if (sl < CAP) g_adj[(size_t)d.x * CAP + sl] = s.x;
        sl = atomicAdd(&g_cur[s.y], 1); if (sl < CAP) g_adj[(size_t)s.y * CAP + sl] = d.y;
        sl = atomicAdd(&g_cur[d.y], 1); if (sl < CAP) g_adj[(size_t)d.y * CAP + sl] = s.y;
        sl = atomicAdd(&g_cur[s.z], 1); if (sl < CAP) g_adj[(size_t)s.z * CAP + sl] = d.z;
        sl = atomicAdd(&g_cur[d.z], 1); if (sl < CAP) g_adj[(size_t)d.z * CAP + sl] = s.z;
        sl = atomicAdd(&g_cur[s.w], 1); if (sl < CAP) g_adj[(size_t)s.w * CAP + sl] = d.w;
        sl = atomicAdd(&g_cur[d.w], 1); if (sl < CAP) g_adj[(size_t)d.w * CAP + sl] = s.w;
    }
}

// ---------------------------------------------------------------------------
// 3) gather aggregation: warp per node, lane owns 4 fp16 cols, fp32 accum.
//    Two independent accumulators break the FADD dependency chain.
// ---------------------------------------------------------------------------
__global__ void __launch_bounds__(256) aggregate_kernel() {
    int node = (blockIdx.x * blockDim.x + threadIdx.x) >> 5;
    int lane = threadIdx.x & 31;
    if (node >= N_NODES) return;

    const int cnt = g_cur[node];                 // true degree
    const int c   = min(cnt, CAP);               // stored entries
    const int* adj = g_adj + (size_t)node * CAP;
    const int col = lane * 4;

    float4 acc0 = make_float4(0.f, 0.f, 0.f, 0.f);
    float4 acc1 = make_float4(0.f, 0.f, 0.f, 0.f);

    int j = 0;
    for (; j + 3 < c; j += 4) {
        int nb0 = __ldg(&adj[j]);
        int nb1 = __ldg(&adj[j + 1]);
        int nb2 = __ldg(&adj[j + 2]);
        int nb3 = __ldg(&adj[j + 3]);
        uint2 u0 = *reinterpret_cast<const uint2*>(g_feath + (size_t)nb0 * D + col);
        uint2 u1 = *reinterpret_cast<const uint2*>(g_feath + (size_t)nb1 * D + col);
        uint2 u2 = *reinterpret_cast<const uint2*>(g_feath + (size_t)nb2 * D + col);
        uint2 u3 = *reinterpret_cast<const uint2*>(g_feath + (size_t)nb3 * D + col);
        float2 a0 = __half22float2(*reinterpret_cast<__half2*>(&u0.x));
        float2 a1 = __half22float2(*reinterpret_cast<__half2*>(&u0.y));
        float2 b0 = __half22float2(*reinterpret_cast<__half2*>(&u1.x));
        float2 b1 = __half22float2(*reinterpret_cast<__half2*>(&u1.y));
        float2 c0 = __half22float2(*reinterpret_cast<__half2*>(&u2.x));
        float2 c1 = __half22float2(*reinterpret_cast<__half2*>(&u2.y));
        float2 d0 = __half22float2(*reinterpret_cast<__half2*>(&u3.x));
        float2 d1 = __half22float2(*reinterpret_cast<__half2*>(&u3.y));
        acc0.x += a0.x + b0.x;  acc1.x += c0.x + d0.x;
        acc0.y += a0.y + b0.y;  acc1.y += c0.y + d0.y;
        acc0.z += a1.x + b1.x;  acc1.z += c1.x + d1.x;
        acc0.w += a1.y + b1.y;  acc1.w += c1.y + d1.y;
    }
    for (; j < c; j++) {
        int nb = __ldg(&adj[j]);
        uint2 u = *reinterpret_cast<const uint2*>(g_feath + (size_t)nb * D + col);
        float2 f0 = __half22float2(*reinterpret_cast<__half2*>(&u.x));
        float2 f1 = __half22float2(*reinterpret_cast<__half2*>(&u.y));
        acc0.x += f0.x; acc0.y += f0.y; acc0.z += f1.x; acc0.w += f1.y;
    }

    float inv = 1.0f / (float)(cnt > 0 ? cnt : 1);
    __half2 o0 = __floats2half2_rn((acc0.x + acc1.x) * inv, (acc0.y + acc1.y) * inv);
    __half2 o1 = __floats2half2_rn((acc0.z + acc1.z) * inv, (acc0.w + acc1.w) * inv);
    uint2 u;
    u.x = *reinterpret_cast<unsigned int*>(&o0);
    u.y = *reinterpret_cast<unsigned int*>(&o1);
    *reinterpret_cast<uint2*>(g_meanh + (size_t)node * D + col) = u;
}

// ---------------------------------------------------------------------------
// 4) HMMA GEMM: out = relu([feat | mean] @ W + b).
//    512 threads, BM=128, BN=128, BK=32 double-buffered via cp.async.
//    (exact R8 configuration: measured 72.0us)
// ---------------------------------------------------------------------------
#define GBM 128
#define GBK2 32
#define A_LD2 40           // 32 + 8 pad
#define W_LD2 136          // 128 + 8 pad

__device__ __forceinline__ void cp16(void* smem_dst, const void* gsrc) {
    unsigned s = (unsigned)__cvta_generic_to_shared(smem_dst);
    asm volatile("cp.async.cg.shared.global [%0], [%1], 16;" :: "r"(s), "l"(gsrc) : "memory");
}
__device__ __forceinline__ void cp_commit() {
    asm volatile("cp.async.commit_group;" ::: "memory");
}
__device__ __forceinline__ void cp_wait0() {
    asm volatile("cp.async.wait_group 0;" ::: "memory");
}

__global__ void __launch_bounds__(512) gemm_kernel(const int*   __restrict__ nodes,
                                                   const float* __restrict__ bias,
                                                   float*       __restrict__ out) {
    __shared__ __align__(16) __half As[2][GBM * A_LD2];   // 20480B
    __shared__ __align__(16) __half Ws[2][GBK2 * W_LD2];  // 17408B

    const int tid = threadIdx.x;
    const int m0  = blockIdx.x * GBM;

    const int arow  = tid >> 2;
    const int acol8 = (tid & 3) * 8;
    const int anode = nodes[min(m0 + arow, N_NODES - 1)];
    const int wrow  = tid >> 4;
    const int wcol8 = (tid & 15) * 8;

    const int wid = tid >> 5;
    const int wm  = wid >> 2;        // 0..3 : rows [wm*32, +32)
    const int wn  = wid & 3;         // 0..3 : cols [wn*32, +32)

    wmma::fragment<wmma::accumulator, 16, 16, 16, float> c[2][2];
    #pragma unroll
    for (int i = 0; i < 2; i++)
        #pragma unroll
        for (int j = 0; j < 2; j++) wmma::fill_fragment(c[i][j], 0.0f);

    // prefetch chunk 0
    {
        const __half* ap = g_feath + (size_t)anode * D + acol8;
        cp16(&As[0][arow * A_LD2 + acol8], ap);
        cp16(&Ws[0][wrow * W_LD2 + wcol8], g_Wh + (size_t)wrow * 128 + wcol8);
        cp_commit();
    }
    cp_wait0();
    __syncthreads();

    #pragma unroll
    for (int kc = 0; kc < 8; kc++) {
        const int buf = kc & 1;
        if (kc < 7) {
            const int kn = kc + 1;
            const __half* basep = (kn < 4)
                ? (g_feath + (size_t)anode * D + kn * 32)
                : (g_meanh + (size_t)anode * D + (kn - 4) * 32);
            cp16(&As[buf ^ 1][arow * A_LD2 + acol8], basep + acol8);
            cp16(&Ws[buf ^ 1][wrow * W_LD2 + wcol8],
                 g_Wh + (size_t)(kn * GBK2 + wrow) * 128 + wcol8);
            cp_commit();
        }

        #pragma unroll
        for (int kkk = 0; kkk < 2; kkk++) {
            wmma::fragment<wmma::matrix_a, 16, 16, 16, __half, wmma::row_major> a[2];
            wmma::load_matrix_sync(a[0], &As[buf][(wm * 32 + 0)  * A_LD2 + kkk * 16], A_LD2);
            wmma::load_matrix_sync(a[1], &As[buf][(wm * 32 + 16) * A_LD2 + kkk * 16], A_LD2);
            wmma::fragment<wmma::matrix_b, 16, 16, 16, __half, wmma::row_major> b[2];
            wmma::load_matrix_sync(b[0], &Ws[buf][(kkk * 16) * W_LD2 + wn * 32],      W_LD2);
            wmma::load_matrix_sync(b[1], &Ws[buf][(kkk * 16) * W_LD2 + wn * 32 + 16], W_LD2);
            #pragma unroll
            for (int i = 0; i < 2; i++)
                #pragma unroll
                for (int j = 0; j < 2; j++)
                    wmma::mma_sync(c[i][j], a[i], b[j], c[i][j]);
        }

        if (kc < 7) {
            cp_wait0();
            __syncthreads();
        }
    }
    __syncthreads();

    // ---- epilogue: two 64-row passes through reused smem (32KB f32 staging)
    float* Cs = reinterpret_cast<float*>(&As[0][0]);   // 64*128*4 = 32768B
    const int erow = tid >> 3;                         // 0..63
    const int eseg = (tid & 7) * 16;                   // 16 cols per thread
    #pragma unroll
    for (int half = 0; half < 2; half++) {
        if ((wm >> 1) == half) {
            #pragma unroll
            for (int i = 0; i < 2; i++)
                #pragma unroll
                for (int j = 0; j < 2; j++)
                    wmma::store_matrix_sync(
                        Cs + ((wm & 1) * 32 + i * 16) * 128 + wn * 32 + j * 16,
                        c[i][j], 128, wmma::mem_row_major);
        }
        __syncthreads();
        int m = m0 + half * 64 + erow;
        if (m < N_NODES) {
            #pragma unroll
            for (int q = 0; q < 4; q++) {
                int col = eseg + q * 4;
                float4 v  = *reinterpret_cast<float4*>(Cs + erow * 128 + col);
                float4 bv = *reinterpret_cast<const float4*>(bias + col);
                v.x = fmaxf(v.x + bv.x, 0.f);
                v.y = fmaxf(v.y + bv.y, 0.f);
                v.z = fmaxf(v.z + bv.z, 0.f);
                v.w = fmaxf(v.w + bv.w, 0.f);
                *reinterpret_cast<float4*>(out + (size_t)m * 128 + col) = v;
            }
        }
        __syncthreads();
    }
}

// ---------------------------------------------------------------------------
// kernel_launch
// Inputs: nodes[i32 100000], features[f32 100000*128], edge_index[i32 2*3.2M],
//         W[f32 256*128], b[f32 128]. Output f32 [100000*128].
// ---------------------------------------------------------------------------
extern "C" void kernel_launch(void* const* d_in, const int* in_sizes, int n_in,
                              void* d_out, int out_size) {
    const int*   nodes = (const int*)d_in[0];
    const float* feat  = (const float*)d_in[1];
    const int*   ei    = (const int*)d_in[2];
    const float* W     = (const float*)d_in[3];
    const float* bias  = (const float*)d_in[4];
    float*       out   = (float*)d_out;

    const int* src = ei;
    const int* dst = ei + N_EDGES;

    convert_kernel<<<3200, 256>>>(feat, W);                       // + zero cursors
    fill_kernel<<<3125, 256>>>(src, dst);
    aggregate_kernel<<<(N_NODES * 32 + 255) / 256, 256>>>();
    gemm_kernel<<<(N_NODES + GBM - 1) / GBM, 512>>>(nodes, bias, out);
}

// round 15
// speedup vs baseline: 2.0939x; 1.0274x over previous
#include <cuda_runtime.h>
#include <cuda_fp16.h>
#include <mma.h>
using namespace nvcuda;

#define N_NODES 100000
#define D 128
#define N_EDGES 3200000
#define CAP 160          // per-node adjacency capacity; Poisson(64) => P(deg>=160) ~ e^-50

// ---- scratch (__device__ globals: allocation-free rule) ----
__device__ __half g_feath[(size_t)N_NODES * D];     // fp16 features
__device__ __half g_meanh[(size_t)N_NODES * D];     // fp16 neighbor means
__device__ __half g_Wh[2 * D * D];                  // fp16 weights
__device__ int    g_cur[N_NODES];                   // degree counters / fill cursors
__device__ int    g_adj[(size_t)N_NODES * CAP];     // bucketed adjacency (64MB)

// ---------------------------------------------------------------------------
// 1) convert features + W to fp16, zero cursors (graph replays -> re-zero)
// ---------------------------------------------------------------------------
__global__ void __launch_bounds__(256) convert_kernel(const float* __restrict__ feat,
                                                      const float* __restrict__ W) {
    int i = blockIdx.x * blockDim.x + threadIdx.x;
    int stride = gridDim.x * blockDim.x;
    const int totalF = N_NODES * D / 4;
    const int totalW = 2 * D * D / 4;
    const float4* f4 = reinterpret_cast<const float4*>(feat);
    const float4* w4 = reinterpret_cast<const float4*>(W);
    for (int k = i; k < totalF; k += stride) {
        float4 v = f4[k];
        __half2 h0 = __floats2half2_rn(v.x, v.y);
        __half2 h1 = __floats2half2_rn(v.z, v.w);
        uint2 u;
        u.x = *reinterpret_cast<unsigned int*>(&h0);
        u.y = *reinterpret_cast<unsigned int*>(&h1);
        *reinterpret_cast<uint2*>(g_feath + (size_t)k * 4) = u;
    }
    for (int k = i; k < totalW; k += stride) {
        float4 v = w4[k];
        __half2 h0 = __floats2half2_rn(v.x, v.y);
        __half2 h1 = __floats2half2_rn(v.z, v.w);
        uint2 u;
        u.x = *reinterpret_cast<unsigned int*>(&h0);
        u.y = *reinterpret_cast<unsigned int*>(&h1);
        *reinterpret_cast<uint2*>(g_Wh + (size_t)k * 4) = u;
    }
    for (int k = i; k < N_NODES; k += stride) g_cur[k] = 0;
}

// ---------------------------------------------------------------------------
// 2) adjacency fill into fixed-stride buckets (no hist/scan needed)
// ---------------------------------------------------------------------------
__global__ void __launch_bounds__(256) fill_kernel(const int* __restrict__ src,
                                                   const int* __restrict__ dst) {
    int i = blockIdx.x * blockDim.x + threadIdx.x;
    int stride = gridDim.x * blockDim.x;
    const int4* s4 = reinterpret_cast<const int4*>(src);
    const int4* d4 = reinterpret_cast<const int4*>(dst);
    for (int e = i; e < N_EDGES / 4; e += stride) {
        int4 s = s4[e], d = d4[e];
        int sl;
        sl = atomicAdd(&g_cur[s.x], 1); if (sl < CAP) g_adj[(size_t)s.x * CAP + sl] = d.x;
        sl = atomicAdd(&g_cur[d.x], 1); if (sl < CAP) g_adj[(size_t)d.x * CAP + sl] = s.x;
        sl = atomicAdd(&g_cur[s.y], 1); if (sl < CAP) g_adj[(size_t)s.y * CAP + sl] = d.y;
        sl = atomicAdd(&g_cur[d.y], 1); if (sl < CAP) g_adj[(size_t)d.y * CAP + sl] = s.y;
        sl = atomicAdd(&g_cur[s.z], 1); if (sl < CAP) g_adj[(size_t)s.z * CAP + sl] = d.z;
        sl = atomicAdd(&g_cur[d.z], 1); if (sl < CAP) g_adj[(size_t)d.z * CAP + sl] = s.z;
        sl = atomicAdd(&g_cur[s.w], 1); if (sl < CAP) g_adj[(size_t)s.w * CAP + sl] = d.w;
        sl = atomicAdd(&g_cur[d.w], 1); if (sl < CAP) g_adj[(size_t)d.w * CAP + sl] = s.w;
    }
}

// ---------------------------------------------------------------------------
// 3) gather aggregation: warp per node, lane owns 4 fp16 cols, fp32 accum.
// ---------------------------------------------------------------------------
__global__ void __launch_bounds__(256) aggregate_kernel() {
    int node = (blockIdx.x * blockDim.x + threadIdx.x) >> 5;
    int lane = threadIdx.x & 31;
    if (node >= N_NODES) return;

    const int cnt = g_cur[node];                 // true degree
    const int c   = min(cnt, CAP);               // stored entries
    const int* adj = g_adj + (size_t)node * CAP;
    const int col = lane * 4;

    float4 acc0 = make_float4(0.f, 0.f, 0.f, 0.f);
    float4 acc1 = make_float4(0.f, 0.f, 0.f, 0.f);

    int j = 0;
    for (; j + 3 < c; j += 4) {
        int nb0 = __ldg(&adj[j]);
        int nb1 = __ldg(&adj[j + 1]);
        int nb2 = __ldg(&adj[j + 2]);
        int nb3 = __ldg(&adj[j + 3]);
        uint2 u0 = *reinterpret_cast<const uint2*>(g_feath + (size_t)nb0 * D + col);
        uint2 u1 = *reinterpret_cast<const uint2*>(g_feath + (size_t)nb1 * D + col);
        uint2 u2 = *reinterpret_cast<const uint2*>(g_feath + (size_t)nb2 * D + col);
        uint2 u3 = *reinterpret_cast<const uint2*>(g_feath + (size_t)nb3 * D + col);
        float2 a0 = __half22float2(*reinterpret_cast<__half2*>(&u0.x));
        float2 a1 = __half22float2(*reinterpret_cast<__half2*>(&u0.y));
        float2 b0 = __half22float2(*reinterpret_cast<__half2*>(&u1.x));
        float2 b1 = __half22float2(*reinterpret_cast<__half2*>(&u1.y));
        float2 c0 = __half22float2(*reinterpret_cast<__half2*>(&u2.x));
        float2 c1 = __half22float2(*reinterpret_cast<__half2*>(&u2.y));
        float2 d0 = __half22float2(*reinterpret_cast<__half2*>(&u3.x));
        float2 d1 = __half22float2(*reinterpret_cast<__half2*>(&u3.y));
        acc0.x += a0.x + b0.x;  acc1.x += c0.x + d0.x;
        acc0.y += a0.y + b0.y;  acc1.y += c0.y + d0.y;
        acc0.z += a1.x + b1.x;  acc1.z += c1.x + d1.x;
        acc0.w += a1.y + b1.y;  acc1.w += c1.y + d1.y;
    }
    for (; j < c; j++) {
        int nb = __ldg(&adj[j]);
        uint2 u = *reinterpret_cast<const uint2*>(g_feath + (size_t)nb * D + col);
        float2 f0 = __half22float2(*reinterpret_cast<__half2*>(&u.x));
        float2 f1 = __half22float2(*reinterpret_cast<__half2*>(&u.y));
        acc0.x += f0.x; acc0.y += f0.y; acc0.z += f1.x; acc0.w += f1.y;
    }

    float inv = 1.0f / (float)(cnt > 0 ? cnt : 1);
    __half2 o0 = __floats2half2_rn((acc0.x + acc1.x) * inv, (acc0.y + acc1.y) * inv);
    __half2 o1 = __floats2half2_rn((acc0.z + acc1.z) * inv, (acc0.w + acc1.w) * inv);
    uint2 u;
    u.x = *reinterpret_cast<unsigned int*>(&o0);
    u.y = *reinterpret_cast<unsigned int*>(&o1);
    *reinterpret_cast<uint2*>(g_meanh + (size_t)node * D + col) = u;
}

// ---------------------------------------------------------------------------
// 4) HMMA GEMM: out = relu([feat | mean] @ W + b).
//    256 threads, BM=64, BN=128, BK=32 double-buffered cp.async.
//    ~94 regs x 256 thr = 24K regs, 27.6KB smem -> 2 CTAs/SM:
//    independent barrier domains overlap each other's stalls.
// ---------------------------------------------------------------------------
#define GBM 64
#define GBK2 32
#define A_LD2 40           // 32 + 8 pad halfs (80B stride)
#define W_LD2 136          // 128 + 8 pad halfs (272B stride)
#define AS_BYTES (2 * GBM * A_LD2 * 2)      // 10240
#define WS_BYTES (2 * GBK2 * W_LD2 * 2)     // 17408

__device__ __forceinline__ void cp16(void* smem_dst, const void* gsrc) {
    unsigned s = (unsigned)__cvta_generic_to_shared(smem_dst);
    asm volatile("cp.async.cg.shared.global [%0], [%1], 16;" :: "r"(s), "l"(gsrc) : "memory");
}
__device__ __forceinline__ void cp_commit() {
    asm volatile("cp.async.commit_group;" ::: "memory");
}
__device__ __forceinline__ void cp_wait0() {
    asm volatile("cp.async.wait_group 0;" ::: "memory");
}

__global__ void __launch_bounds__(256) gemm_kernel(const int*   __restrict__ nodes,
                                                   const float* __restrict__ bias,
                                                   float*       __restrict__ out) {
    __shared__ __align__(16) unsigned char smem_raw[AS_BYTES + WS_BYTES];  // 27648B
    __half* Asb = reinterpret_cast<__half*>(smem_raw);                 // [2][64*40]
    __half* Wsb = reinterpret_cast<__half*>(smem_raw + AS_BYTES);      // [2][32*136]

    const int tid = threadIdx.x;
    const int m0  = blockIdx.x * GBM;

    // A staging: 64 rows x 32 halfs (64B) = 256 x 16B -> 1 cp16/thread
    const int arow  = tid >> 2;
    const int acol8 = (tid & 3) * 8;
    const int anode = nodes[min(m0 + arow, N_NODES - 1)];
    // W staging: 32 rows x 128 halfs = 512 x 16B -> 2 cp16/thread

    const int wid = tid >> 5;
    const int wm  = wid >> 2;        // 0..1 : rows [wm*32, +32)
    const int wn  = wid & 3;         // 0..3 : cols [wn*32, +32)

    wmma::fragment<wmma::accumulator, 16, 16, 16, float> c[2][2];
    #pragma unroll
    for (int i = 0; i < 2; i++)
        #pragma unroll
        for (int j = 0; j < 2; j++) wmma::fill_fragment(c[i][j], 0.0f);

    // prefetch chunk 0
    {
        cp16(Asb + arow * A_LD2 + acol8, g_feath + (size_t)anode * D + acol8);
        #pragma unroll
        for (int j = 0; j < 2; j++) {
            int g    = tid * 2 + j;
            int wrow = g >> 4;
            int wc8  = (g & 15) * 8;
            cp16(Wsb + wrow * W_LD2 + wc8, g_Wh + (size_t)wrow * 128 + wc8);
        }
        cp_commit();
    }
    cp_wait0();
    __syncthreads();

    #pragma unroll
    for (int kc = 0; kc < 8; kc++) {
        const int buf = kc & 1;
        if (kc < 7) {
            const int kn = kc + 1;
            const __half* basep = (kn < 4)
                ? (g_feath + (size_t)anode * D + kn * 32)
                : (g_meanh + (size_t)anode * D + (kn - 4) * 32);
            cp16(Asb + (buf ^ 1) * GBM * A_LD2 + arow * A_LD2 + acol8, basep + acol8);
            #pragma unroll
            for (int j = 0; j < 2; j++) {
                int g    = tid * 2 + j;
                int wrow = g >> 4;
                int wc8  = (g & 15) * 8;
                cp16(Wsb + (buf ^ 1) * GBK2 * W_LD2 + wrow * W_LD2 + wc8,
                     g_Wh + (size_t)(kn * GBK2 + wrow) * 128 + wc8);
            }
            cp_commit();
        }

        const __half* Ab = Asb + buf * GBM * A_LD2;
        const __half* Wb = Wsb + buf * GBK2 * W_LD2;
        #pragma unroll
        for (int kkk = 0; kkk < 2; kkk++) {
            wmma::fragment<wmma::matrix_a, 16, 16, 16, __half, wmma::row_major> a[2];
            wmma::load_matrix_sync(a[0], Ab + (wm * 32 + 0)  * A_LD2 + kkk * 16, A_LD2);
            wmma::load_matrix_sync(a[1], Ab + (wm * 32 + 16) * A_LD2 + kkk * 16, A_LD2);
            wmma::fragment<wmma::matrix_b, 16, 16, 16, __half, wmma::row_major> b[2];
            wmma::load_matrix_sync(b[0], Wb + (kkk * 16) * W_LD2 + wn * 32,      W_LD2);
            wmma::load_matrix_sync(b[1], Wb + (kkk * 16) * W_LD2 + wn * 32 + 16, W_LD2);
            #pragma unroll
            for (int i = 0; i < 2; i++)
                #pragma unroll
                for (int j = 0; j < 2; j++)
                    wmma::mma_sync(c[i][j], a[i], b[j], c[i][j]);
        }

        if (kc < 7) {
            cp_wait0();
            __syncthreads();
        }
    }
    __syncthreads();

    // ---- epilogue: two 32-row passes through reused smem (16KB f32 staging)
    float* Cs = reinterpret_cast<float*>(smem_raw);    // 32*128*4 = 16384B
    const int erow = tid >> 3;                         // 0..31
    const int eseg = (tid & 7) * 16;                   // 16 cols per thread
    #pragma unroll
    for (int half = 0; half < 2; half++) {
        if (wm == half) {
            #pragma unroll
            for (int i = 0; i < 2; i++)
                #pragma unroll
                for (int j = 0; j < 2; j++)
                    wmma::store_matrix_sync(Cs + (i * 16) * 128 + wn * 32 + j * 16,
                                            c[i][j], 128, wmma::mem_row_major);
        }
        __syncthreads();
        int m = m0 + half * 32 + erow;
        if (m < N_NODES) {
            #pragma unroll
            for (int q = 0; q < 4; q++) {
                int col = eseg + q * 4;
                float4 v  = *reinterpret_cast<float4*>(Cs + erow * 128 + col);
                float4 bv = *reinterpret_cast<const float4*>(bias + col);
                v.x = fmaxf(v.x + bv.x, 0.f);
                v.y = fmaxf(v.y + bv.y, 0.f);
                v.z = fmaxf(v.z + bv.z, 0.f);
                v.w = fmaxf(v.w + bv.w, 0.f);
                *reinterpret_cast<float4*>(out + (size_t)m * 128 + col) = v;
            }
        }
        __syncthreads();
    }
}

// ---------------------------------------------------------------------------
// kernel_launch
// Inputs: nodes[i32 100000], features[f32 100000*128], edge_index[i32 2*3.2M],
//         W[f32 256*128], b[f32 128]. Output f32 [100000*128].
// ---------------------------------------------------------------------------
extern "C" void kernel_launch(void* const* d_in, const int* in_sizes, int n_in,
                              void* d_out, int out_size) {
    const int*   nodes = (const int*)d_in[0];
    const float* feat  = (const float*)d_in[1];
    const int*   ei    = (const int*)d_in[2];
    const float* W     = (const float*)d_in[3];
    const float* bias  = (const float*)d_in[4];
    float*       out   = (float*)d_out;

    const int* src = ei;
    const int* dst = ei + N_EDGES;

    convert_kernel<<<3200, 256>>>(feat, W);                       // + zero cursors
    fill_kernel<<<3125, 256>>>(src, dst);
    aggregate_kernel<<<(N_NODES * 32 + 255) / 256, 256>>>();
    gemm_kernel<<<(N_NODES + GBM - 1) / GBM, 256>>>(nodes, bias, out);
}

// round 17
// speedup vs baseline: 2.1425x; 1.0232x over previous
#include <cuda_runtime.h>
#include <cuda_fp16.h>
#include <mma.h>
using namespace nvcuda;

#define N_NODES 100000
#define D 128
#define N_EDGES 3200000
#define CAP 160          // per-node adjacency capacity; Poisson(64) => P(deg>=160) ~ e^-50

// ---- scratch (__device__ globals: allocation-free rule) ----
__device__ __half g_feath[(size_t)N_NODES * D];     // fp16 features
__device__ __half g_meanh[(size_t)N_NODES * D];     // fp16 neighbor means
__device__ __half g_Wh[2 * D * D];                  // fp16 weights
__device__ int    g_cur[N_NODES];                   // degree counters / fill cursors
__device__ int    g_adj[(size_t)N_NODES * CAP];     // bucketed adjacency (64MB)

// ---------------------------------------------------------------------------
// 1) convert features + W to fp16, zero cursors (graph replays -> re-zero)
// ---------------------------------------------------------------------------
__global__ void __launch_bounds__(256) convert_kernel(const float* __restrict__ feat,
                                                      const float* __restrict__ W) {
    int i = blockIdx.x * blockDim.x + threadIdx.x;
    int stride = gridDim.x * blockDim.x;
    const int totalF = N_NODES * D / 4;
    const int totalW = 2 * D * D / 4;
    const float4* f4 = reinterpret_cast<const float4*>(feat);
    const float4* w4 = reinterpret_cast<const float4*>(W);
    for (int k = i; k < totalF; k += stride) {
        float4 v = f4[k];
        __half2 h0 = __floats2half2_rn(v.x, v.y);
        __half2 h1 = __floats2half2_rn(v.z, v.w);
        uint2 u;
        u.x = *reinterpret_cast<unsigned int*>(&h0);
        u.y = *reinterpret_cast<unsigned int*>(&h1);
        *reinterpret_cast<uint2*>(g_feath + (size_t)k * 4) = u;
    }
    for (int k = i; k < totalW; k += stride) {
        float4 v = w4[k];
        __half2 h0 = __floats2half2_rn(v.x, v.y);
        __half2 h1 = __floats2half2_rn(v.z, v.w);
        uint2 u;
        u.x = *reinterpret_cast<unsigned int*>(&h0);
        u.y = *reinterpret_cast<unsigned int*>(&h1);
        *reinterpret_cast<uint2*>(g_Wh + (size_t)k * 4) = u;
    }
    for (int k = i; k < N_NODES; k += stride) g_cur[k] = 0;
}

// ---------------------------------------------------------------------------
// 2) adjacency fill into fixed-stride buckets (no hist/scan needed)
// ---------------------------------------------------------------------------
__global__ void __launch_bounds__(256) fill_kernel(const int* __restrict__ src,
                                                   const int* __restrict__ dst) {
    int i = blockIdx.x * blockDim.x + threadIdx.x;
    int stride = gridDim.x * blockDim.x;
    const int4* s4 = reinterpret_cast<const int4*>(src);
    const int4* d4 = reinterpret_cast<const int4*>(dst);
    for (int e = i; e < N_EDGES / 4; e += stride) {
        int4 s = s4[e], d = d4[e];
        int sl;
        sl = atomicAdd(&g_cur[s.x], 1); if (sl < CAP) g_adj[(size_t)s.x * CAP + sl] = d.x;
        sl = atomicAdd(&g_cur[d.x], 1); if (sl < CAP) g_adj[(size_t)d.x * CAP + sl] = s.x;
        sl = atomicAdd(&g_cur[s.y], 1); if (sl < CAP) g_adj[(size_t)s.y * CAP + sl] = d.y;
        sl = atomicAdd(&g_cur[d.y], 1); if (sl < CAP) g_adj[(size_t)d.y * CAP + sl] = s.y;
        sl = atomicAdd(&g_cur[s.z], 1); if (sl < CAP) g_adj[(size_t)s.z * CAP + sl] = d.z;
        sl = atomicAdd(&g_cur[d.z], 1); if (sl < CAP) g_adj[(size_t)d.z * CAP + sl] = s.z;
        sl = atomicAdd(&g_cur[s.w], 1); if (sl < CAP) g_adj[(size_t)s.w * CAP + sl] = d.w;
        sl = atomicAdd(&g_cur[d.w], 1); if (sl < CAP) g_adj[(size_t)d.w * CAP + sl] = s.w;
    }
}

// ---------------------------------------------------------------------------
// 3) gather aggregation: warp per node, lane owns 4 fp16 cols, fp32 accum.
// ---------------------------------------------------------------------------
__global__ void __launch_bounds__(256) aggregate_kernel() {
    int node = (blockIdx.x * blockDim.x + threadIdx.x) >> 5;
    int lane = threadIdx.x & 31;
    if (node >= N_NODES) return;

    const int cnt = g_cur[node];                 // true degree
    const int c   = min(cnt, CAP);               // stored entries
    const int* adj = g_adj + (size_t)node * CAP;
    const int col = lane * 4;

    float4 acc0 = make_float4(0.f, 0.f, 0.f, 0.f);
    float4 acc1 = make_float4(0.f, 0.f, 0.f, 0.f);

    int j = 0;
    for (; j + 3 < c; j += 4) {
        int nb0 = __ldg(&adj[j]);
        int nb1 = __ldg(&adj[j + 1]);
        int nb2 = __ldg(&adj[j + 2]);
        int nb3 = __ldg(&adj[j + 3]);
        uint2 u0 = *reinterpret_cast<const uint2*>(g_feath + (size_t)nb0 * D + col);
        uint2 u1 = *reinterpret_cast<const uint2*>(g_feath + (size_t)nb1 * D + col);
        uint2 u2 = *reinterpret_cast<const uint2*>(g_feath + (size_t)nb2 * D + col);
        uint2 u3 = *reinterpret_cast<const uint2*>(g_feath + (size_t)nb3 * D + col);
        float2 a0 = __half22float2(*reinterpret_cast<__half2*>(&u0.x));
        float2 a1 = __half22float2(*reinterpret_cast<__half2*>(&u0.y));
        float2 b0 = __half22float2(*reinterpret_cast<__half2*>(&u1.x));
        float2 b1 = __half22float2(*reinterpret_cast<__half2*>(&u1.y));
        float2 c0 = __half22float2(*reinterpret_cast<__half2*>(&u2.x));
        float2 c1 = __half22float2(*reinterpret_cast<__half2*>(&u2.y));
        float2 d0 = __half22float2(*reinterpret_cast<__half2*>(&u3.x));
        float2 d1 = __half22float2(*reinterpret_cast<__half2*>(&u3.y));
        acc0.x += a0.x + b0.x;  acc1.x += c0.x + d0.x;
        acc0.y += a0.y + b0.y;  acc1.y += c0.y + d0.y;
        acc0.z += a1.x + b1.x;  acc1.z += c1.x + d1.x;
        acc0.w += a1.y + b1.y;  acc1.w += c1.y + d1.y;
    }
    for (; j < c; j++) {
        int nb = __ldg(&adj[j]);
        uint2 u = *reinterpret_cast<const uint2*>(g_feath + (size_t)nb * D + col);
        float2 f0 = __half22float2(*reinterpret_cast<__half2*>(&u.x));
        float2 f1 = __half22float2(*reinterpret_cast<__half2*>(&u.y));
        acc0.x += f0.x; acc0.y += f0.y; acc0.z += f1.x; acc0.w += f1.y;
    }

    float inv = 1.0f / (float)(cnt > 0 ? cnt : 1);
    __half2 o0 = __floats2half2_rn((acc0.x + acc1.x) * inv, (acc0.y + acc1.y) * inv);
    __half2 o1 = __floats2half2_rn((acc0.z + acc1.z) * inv, (acc0.w + acc1.w) * inv);
    uint2 u;
    u.x = *reinterpret_cast<unsigned int*>(&o0);
    u.y = *reinterpret_cast<unsigned int*>(&o1);
    *reinterpret_cast<uint2*>(g_meanh + (size_t)node * D + col) = u;
}

// ---------------------------------------------------------------------------
// 4) HMMA GEMM: out = relu([feat | mean] @ W + b).
//    256 threads, BM=64, BN=128, BK=32, THREE-stage cp.async pipeline,
//    __launch_bounds__(256,3) -> <=85 regs -> 3 CTAs/SM.
// ---------------------------------------------------------------------------
#define GBM 64
#define GBK2 32
#define A_LD2 40           // 32 + 8 pad halfs (80B stride)
#define W_LD2 136          // 128 + 8 pad halfs (272B stride)
#define A_BUF (GBM * A_LD2)                 // halfs per A stage
#define W_BUF (GBK2 * W_LD2)                // halfs per W stage
#define AS_BYTES (3 * A_BUF * 2)            // 15360
#define WS_BYTES (3 * W_BUF * 2)            // 26112

__device__ __forceinline__ void cp16(void* smem_dst, const void* gsrc) {
    unsigned s = (unsigned)__cvta_generic_to_shared(smem_dst);
    asm volatile("cp.async.cg.shared.global [%0], [%1], 16;" :: "r"(s), "l"(gsrc) : "memory");
}
__device__ __forceinline__ void cp_commit() {
    asm volatile("cp.async.commit_group;" ::: "memory");
}
__device__ __forceinline__ void cp_wait1() {
    asm volatile("cp.async.wait_group 1;" ::: "memory");
}

__global__ void __launch_bounds__(256, 3) gemm_kernel(const int*   __restrict__ nodes,
                                                      const float* __restrict__ bias,
                                                      float*       __restrict__ out) {
    __shared__ __align__(16) unsigned char smem_raw[AS_BYTES + WS_BYTES];  // 41472B
    __half* Asb = reinterpret_cast<__half*>(smem_raw);                 // [3][64*40]
    __half* Wsb = reinterpret_cast<__half*>(smem_raw + AS_BYTES);      // [3][32*136]

    const int tid = threadIdx.x;
    const int m0  = blockIdx.x * GBM;

    // A staging: 64 rows x 32 halfs (64B) = 256 x 16B -> 1 cp16/thread
    const int arow  = tid >> 2;
    const int acol8 = (tid & 3) * 8;
    const int anode = nodes[min(m0 + arow, N_NODES - 1)];
    // W staging: 32 rows x 128 halfs = 512 x 16B -> 2 cp16/thread

    const int wid = tid >> 5;
    const int wm  = wid >> 2;        // 0..1 : rows [wm*32, +32)
    const int wn  = wid & 3;         // 0..3 : cols [wn*32, +32)

    wmma::fragment<wmma::accumulator, 16, 16, 16, float> c[2][2];
    #pragma unroll
    for (int i = 0; i < 2; i++)
        #pragma unroll
        for (int j = 0; j < 2; j++) wmma::fill_fragment(c[i][j], 0.0f);

    // prefetch chunks 0 and 1 (one commit group each)
    #pragma unroll
    for (int kn = 0; kn < 2; kn++) {
        const __half* basep = g_feath + (size_t)anode * D + kn * 32;
        cp16(Asb + kn * A_BUF + arow * A_LD2 + acol8, basep + acol8);
        #pragma unroll
        for (int j = 0; j < 2; j++) {
            int g    = tid * 2 + j;
            int wrow = g >> 4;
            int wc8  = (g & 15) * 8;
            cp16(Wsb + kn * W_BUF + wrow * W_LD2 + wc8,
                 g_Wh + (size_t)(kn * GBK2 + wrow) * 128 + wc8);
        }
        cp_commit();
    }

    #pragma unroll
    for (int kc = 0; kc < 8; kc++) {
        const int buf = kc % 3;
        cp_wait1();              // chunk kc landed (kc+1 may be in flight)
        __syncthreads();         // all warps done with chunk kc-1's buffer

        if (kc + 2 < 8) {        // prefetch chunk kc+2 into buf (kc+2)%3
            const int kn  = kc + 2;
            const int nbuf = kn % 3;
            const __half* basep = (kn < 4)
                ? (g_feath + (size_t)anode * D + kn * 32)
                : (g_meanh + (size_t)anode * D + (kn - 4) * 32);
            cp16(Asb + nbuf * A_BUF + arow * A_LD2 + acol8, basep + acol8);
            #pragma unroll
            for (int j = 0; j < 2; j++) {
                int g    = tid * 2 + j;
                int wrow = g >> 4;
                int wc8  = (g & 15) * 8;
                cp16(Wsb + nbuf * W_BUF + wrow * W_LD2 + wc8,
                     g_Wh + (size_t)(kn * GBK2 + wrow) * 128 + wc8);
            }
        }
        cp_commit();             // commit every iteration (keeps group counts aligned)

        const __half* Ab = Asb + buf * A_BUF;
        const __half* Wb = Wsb + buf * W_BUF;
        #pragma unroll
        for (int kkk = 0; kkk < 2; kkk++) {
            wmma::fragment<wmma::matrix_a, 16, 16, 16, __half, wmma::row_major> a[2];
            wmma::load_matrix_sync(a[0], Ab + (wm * 32 + 0)  * A_LD2 + kkk * 16, A_LD2);
            wmma::load_matrix_sync(a[1], Ab + (wm * 32 + 16) * A_LD2 + kkk * 16, A_LD2);
            wmma::fragment<wmma::matrix_b, 16, 16, 16, __half, wmma::row_major> b[2];
            wmma::load_matrix_sync(b[0], Wb + (kkk * 16) * W_LD2 + wn * 32,      W_LD2);
            wmma::load_matrix_sync(b[1], Wb + (kkk * 16) * W_LD2 + wn * 32 + 16, W_LD2);
            #pragma unroll
            for (int i = 0; i < 2; i++)
                #pragma unroll
                for (int j = 0; j < 2; j++)
                    wmma::mma_sync(c[i][j], a[i], b[j], c[i][j]);
        }
    }
    __syncthreads();

    // ---- epilogue: two 32-row passes through reused smem (16KB f32 staging)
    float* Cs = reinterpret_cast<float*>(smem_raw);    // 32*128*4 = 16384B
    const int erow = tid >> 3;                         // 0..31
    const int eseg = (tid & 7) * 16;                   // 16 cols per thread
    #pragma unroll
    for (int half = 0; half < 2; half++) {
        if (wm == half) {
            #pragma unroll
            for (int i = 0; i < 2; i++)
                #pragma unroll
                for (int j = 0; j < 2; j++)
                    wmma::store_matrix_sync(Cs + (i * 16) * 128 + wn * 32 + j * 16,
                                            c[i][j], 128, wmma::mem_row_major);
        }
        __syncthreads();
        int m = m0 + half * 32 + erow;
        if (m < N_NODES) {
            #pragma unroll
            for (int q = 0; q < 4; q++) {
                int col = eseg + q * 4;
                float4 v  = *reinterpret_cast<float4*>(Cs + erow * 128 + col);
                float4 bv = *reinterpret_cast<const float4*>(bias + col);
                v.x = fmaxf(v.x + bv.x, 0.f);
                v.y = fmaxf(v.y + bv.y, 0.f);
                v.z = fmaxf(v.z + bv.z, 0.f);
                v.w = fmaxf(v.w + bv.w, 0.f);
                *reinterpret_cast<float4*>(out + (size_t)m * 128 + col) = v;
            }
        }
        __syncthreads();
    }
}

// ---------------------------------------------------------------------------
// kernel_launch
// Inputs: nodes[i32 100000], features[f32 100000*128], edge_index[i32 2*3.2M],
//         W[f32 256*128], b[f32 128]. Output f32 [100000*128].
// ---------------------------------------------------------------------------
extern "C" void kernel_launch(void* const* d_in, const int* in_sizes, int n_in,
                              void* d_out, int out_size) {
    const int*   nodes = (const int*)d_in[0];
    const float* feat  = (const float*)d_in[1];
    const int*   ei    = (const int*)d_in[2];
    const float* W     = (const float*)d_in[3];
    const float* bias  = (const float*)d_in[4];
    float*       out   = (float*)d_out;

    const int* src = ei;
    const int* dst = ei + N_EDGES;

    convert_kernel<<<3200, 256>>>(feat, W);                       // + zero cursors
    fill_kernel<<<3125, 256>>>(src, dst);
    aggregate_kernel<<<(N_NODES * 32 + 255) / 256, 256>>>();
    gemm_kernel<<<(N_NODES + GBM - 1) / GBM, 256>>>(nodes, bias, out);
}